// round 12
// baseline (speedup 1.0000x reference)
#include <cuda_runtime.h>
#include <cstdint>

#define NB   16
#define FIN  64
#define FOUT 128
#define NP   2048
#define KNN  20
#define NPTS (NB * NP)            /* 32768 */
#define EDGES (NPTS * KNN)        /* 655360 */

typedef unsigned long long u64;

// ---------------- scratch (device globals: no allocations allowed) ----------
__device__ float    g_sq[NPTS];
__device__ unsigned g_key[(size_t)NPTS * NP];   // 256 MB, pre-transformed sortable uints
__device__ int      g_idx[NPTS * KNN];
__device__ float    g_A[FIN * FOUT];            // (W1-W2)^T  [f][o]
__device__ float    g_C[FIN * FOUT];            // W2^T       [f][o]
__device__ float    g_P[NPTS * FOUT];
__device__ float    g_Q[NPTS * FOUT];
__device__ float    g_ymax[NPTS * FOUT];
__device__ float    g_ymin[NPTS * FOUT];
__device__ float    g_S1[FOUT];
__device__ float    g_S2[FOUT];
__device__ float    g_scale[FOUT];
__device__ float    g_shift[FOUT];

// ---------------- f32x2 helpers (Blackwell packed fp32 FMA) -----------------
__device__ __forceinline__ u64 fma2(u64 a, u64 b, u64 c) {
    u64 d;
    asm("fma.rn.f32x2 %0, %1, %2, %3;" : "=l"(d) : "l"(a), "l"(b), "l"(c));
    return d;
}
__device__ __forceinline__ u64 dupf(float a) {
    u64 d;
    unsigned u = __float_as_uint(a);
    asm("mov.b64 %0, {%1, %1};" : "=l"(d) : "r"(u));
    return d;
}
__device__ __forceinline__ float2 unpack2(u64 d) {
    unsigned lo, hi;
    asm("mov.b64 {%0, %1}, %2;" : "=r"(lo), "=r"(hi) : "l"(d));
    return make_float2(__uint_as_float(lo), __uint_as_float(hi));
}
// monotone float -> unsigned-sortable transform
__device__ __forceinline__ unsigned tkey(float f) {
    unsigned b = __float_as_uint(f);
    return ((int)b < 0) ? ~b : (b | 0x80000000u);
}

// ---------------- kernels ---------------------------------------------------

__global__ void k_zero() {
    int t = threadIdx.x;
    if (t < FOUT) { g_S1[t] = 0.f; g_S2[t] = 0.f; }
}

// sq[b,n] = sum_f x^2
__global__ void k_sq(const float* __restrict__ x) {
    int gp = blockIdx.x * blockDim.x + threadIdx.x;
    if (gp >= NPTS) return;
    int b = gp >> 11, n = gp & (NP - 1);
    const float* p = x + (size_t)b * FIN * NP + n;
    float s = 0.f;
#pragma unroll
    for (int f = 0; f < FIN; f++) { float v = p[(size_t)f * NP]; s = fmaf(v, v, s); }
    g_sq[gp] = s;
}

// Transpose weights: g_A[f][o] = W[o][f]-W[o][64+f], g_C[f][o] = W[o][64+f]
__global__ void k_prep(const float* __restrict__ W) {
    int id = blockIdx.x * 256 + threadIdx.x;   // 0..8191
    if (id >= FIN * FOUT) return;
    int f = id >> 7, o = id & 127;
    float w1 = W[o * 128 + f], w2 = W[o * 128 + 64 + f];
    g_A[f * 128 + o] = w1 - w2;
    g_C[f * 128 + o] = w2;
}

// Symmetric Gram, lower-triangle 128x128 tiles, key = transform(sq[m]-2G)
// stored as sortable unsigned (saves the per-key transform in k_select and
// keeps histogram bins well-spread -> no shared-atomic serialization).
__global__ __launch_bounds__(256, 2) void k_gram(const float* __restrict__ x) {
    extern __shared__ float sm[];
    float* As = sm;               // [64][128]
    float* Bs = sm + 64 * 128;    // [64][128]
    int b = blockIdx.z;
    int kk = blockIdx.x;
    int ti = (int)((sqrtf(8.f * kk + 1.f) - 1.f) * 0.5f);
    while ((ti + 1) * (ti + 2) / 2 <= kk) ti++;
    while (ti * (ti + 1) / 2 > kk) ti--;
    int tj = kk - ti * (ti + 1) / 2;
    int n0 = ti * 128;            // rows
    int m0 = tj * 128;            // cols
    int tid = threadIdx.x;
    const float* xb = x + (size_t)b * FIN * NP;
#pragma unroll
    for (int i = 0; i < 8; i++) {
        int flat = (tid + 256 * i) * 4;
        int k = flat >> 7;
        int c = flat & 127;
        *(float4*)(As + k * 128 + c) = *(const float4*)(xb + (size_t)k * NP + n0 + c);
        *(float4*)(Bs + k * 128 + c) = *(const float4*)(xb + (size_t)k * NP + m0 + c);
    }
    __syncthreads();
    int tx = tid & 15, ty = tid >> 4;
    u64 acc[8][4];
#pragma unroll
    for (int i = 0; i < 8; i++)
#pragma unroll
        for (int j = 0; j < 4; j++) acc[i][j] = 0ull;

#pragma unroll 4
    for (int k = 0; k < 64; k++) {
        float4 a0 = *(float4*)(As + k * 128 + ty * 8);
        float4 a1 = *(float4*)(As + k * 128 + ty * 8 + 4);
        ulonglong2 bv0 = *(ulonglong2*)(Bs + k * 128 + tx * 8);
        ulonglong2 bv1 = *(ulonglong2*)(Bs + k * 128 + tx * 8 + 4);
        float av[8] = {a0.x, a0.y, a0.z, a0.w, a1.x, a1.y, a1.z, a1.w};
        u64 bv[4] = {bv0.x, bv0.y, bv1.x, bv1.y};
#pragma unroll
        for (int i = 0; i < 8; i++) {
            u64 ad = dupf(av[i]);
#pragma unroll
            for (int j = 0; j < 4; j++) acc[i][j] = fma2(ad, bv[j], acc[i][j]);
        }
    }
    float gf[8][8];
#pragma unroll
    for (int i = 0; i < 8; i++)
#pragma unroll
        for (int j = 0; j < 4; j++) {
            float2 p = unpack2(acc[i][j]);
            gf[i][2 * j] = p.x; gf[i][2 * j + 1] = p.y;
        }
    // direct tile
    {
        float sqm[8];
        *(float4*)sqm       = *(const float4*)(g_sq + b * NP + m0 + tx * 8);
        *(float4*)(sqm + 4) = *(const float4*)(g_sq + b * NP + m0 + tx * 8 + 4);
#pragma unroll
        for (int i = 0; i < 8; i++) {
            unsigned v[8];
#pragma unroll
            for (int k = 0; k < 8; k++) v[k] = tkey(fmaf(gf[i][k], -2.f, sqm[k]));
            unsigned* op = g_key + ((size_t)(b * NP + n0 + ty * 8 + i)) * NP + m0 + tx * 8;
            *(uint4*)op       = *(uint4*)v;
            *(uint4*)(op + 4) = *(uint4*)(v + 4);
        }
    }
    // transposed tile (off-diagonal only)
    if (ti != tj) {
        __syncthreads();
        int s = tid;
        float* slots = sm;
#pragma unroll
        for (int k = 0; k < 8; k++)
#pragma unroll
            for (int i = 0; i < 8; i++)
                slots[s * 65 + k * 8 + ((i + s) & 7)] = gf[i][k];
        __syncthreads();
        int s2 = ((tid & 15) << 4) | (tid >> 4);
        float sqn[8];
        *(float4*)sqn       = *(const float4*)(g_sq + b * NP + n0 + tx * 8);
        *(float4*)(sqn + 4) = *(const float4*)(g_sq + b * NP + n0 + tx * 8 + 4);
#pragma unroll
        for (int r = 0; r < 8; r++) {
            unsigned v[8];
#pragma unroll
            for (int c = 0; c < 8; c++) {
                float w = slots[s2 * 65 + r * 8 + ((c + s2) & 7)];
                v[c] = tkey(fmaf(w, -2.f, sqn[c]));
            }
            unsigned* op = g_key + ((size_t)(b * NP + m0 + ty * 8 + r)) * NP + n0 + tx * 8;
            *(uint4*)op       = *(uint4*)v;
            *(uint4*)(op + 4) = *(uint4*)(v + 4);
        }
    }
}

// Sampling-threshold top-20 select. 256 uniform samples (1/thread) -> 2-round
// radix on samples locates the 8th-smallest sample's 16-bit prefix tau.
// Candidates = keys with prefix <= tau (>=9 guaranteed; ~68 expected); exact
// (u,idx)-lex rank on candidates = stable-argsort top-20. Prefix dominance:
// every non-candidate > every candidate. Fallback (<20 or >256 cands, ~0.3%):
// full 2-round radix (verified R6 path).
#define CAND_MAX 256
__global__ __launch_bounds__(256) void k_select() {
    int gp = blockIdx.x;                       // b*NP + n
    int n  = gp & (NP - 1);
    const uint4* row4 = (const uint4*)(g_key + (size_t)gp * NP);
    __shared__ unsigned hist[256];
    __shared__ unsigned cand_u[CAND_MAX];
    __shared__ int      cand_m[CAND_MAX];
    __shared__ unsigned wsum[8];
    __shared__ int s_cand, s_b1, s_c1, s_b2, s_c2, s_sel;
    int t = threadIdx.x;
    int lane = t & 31;

    unsigned u[8];
    {
        uint4 a = __ldcs(row4 + t * 2);
        uint4 c = __ldcs(row4 + t * 2 + 1);
        u[0] = a.x; u[1] = a.y; u[2] = a.z; u[3] = a.w;
        u[4] = c.x; u[5] = c.y; u[6] = c.z; u[7] = c.w;
        int m0 = t * 8;
#pragma unroll
        for (int i = 0; i < 8; i++)
            if (m0 + i == n) u[i] = 0xFFFFFFFFu;
    }

    // ---- sample phase: 256 samples = u[0] of each thread, find 8th smallest
    hist[t] = 0u;
    if (t == 0) s_cand = 0;
    __syncthreads();
    atomicAdd(&hist[u[0] >> 24], 1u);
    __syncthreads();
    {   // scan 1: bin containing sample-rank 8 (0-indexed)
        unsigned cnt = hist[t];
        unsigned v = cnt;
#pragma unroll
        for (int d = 1; d < 32; d <<= 1) {
            unsigned o = __shfl_up_sync(0xFFFFFFFFu, v, d);
            if (lane >= d) v += o;
        }
        if (lane == 31) wsum[t >> 5] = v;
        __syncthreads();
        unsigned woff = 0;
        for (int w = 0; w < (t >> 5); w++) woff += wsum[w];
        unsigned incl = v + woff;
        unsigned excl = incl - cnt;
        if (excl <= 8u && incl > 8u) { s_b1 = t; s_c1 = (int)excl; }
    }
    __syncthreads();
    unsigned b1s = (unsigned)s_b1;
    int c1s = s_c1;
    hist[t] = 0u;
    __syncthreads();
    if ((u[0] >> 24) == b1s) atomicAdd(&hist[(u[0] >> 16) & 255u], 1u);
    __syncthreads();
    {   // scan 2: refine within bin b1s to sample-rank (8 - c1s)
        unsigned cnt = hist[t];
        unsigned v = cnt;
#pragma unroll
        for (int d = 1; d < 32; d <<= 1) {
            unsigned o = __shfl_up_sync(0xFFFFFFFFu, v, d);
            if (lane >= d) v += o;
        }
        if (lane == 31) wsum[t >> 5] = v;
        __syncthreads();
        unsigned woff = 0;
        for (int w = 0; w < (t >> 5); w++) woff += wsum[w];
        unsigned incl = v + woff;
        unsigned excl = incl - cnt;
        int r = 8 - c1s;
        if ((int)excl <= r && (int)incl > r) s_b2 = t;
    }
    __syncthreads();
    unsigned tpre = (b1s << 8) | (unsigned)s_b2;   // 16-bit threshold prefix

    // ---- collection: keys with 16-bit prefix <= tpre
#pragma unroll
    for (int i = 0; i < 8; i++) {
        if ((u[i] >> 16) <= tpre) {
            int c = atomicAdd(&s_cand, 1);
            if (c < CAND_MAX) { cand_u[c] = u[i]; cand_m[c] = t * 8 + i; }
        }
    }
    __syncthreads();
    int cc = s_cand;
    int* out = g_idx + gp * KNN;

    if (cc >= KNN && cc <= CAND_MAX) {
        // exact rank among candidates; top-20 is provably inside
        for (int c = t; c < cc; c += 256) {
            unsigned uc = cand_u[c];
            int mc = cand_m[c];
            int rank = 0;
            for (int j = 0; j < cc; j++) {
                unsigned uj = cand_u[j];
                rank += (uj < uc || (uj == uc && cand_m[j] < mc)) ? 1 : 0;
            }
            if (rank < KNN) out[rank] = mc;
        }
        return;
    }

    // ---------------- fallback: full 2-round radix (rare) -------------------
    hist[t] = 0u;
    if (t == 0) { s_sel = 0; s_cand = 0; }
    __syncthreads();
#pragma unroll
    for (int i = 0; i < 8; i++) {
        unsigned bin = u[i] >> 24;
        unsigned peers = __match_any_sync(0xFFFFFFFFu, bin);
        if ((peers & ((1u << lane) - 1u)) == 0u)
            atomicAdd(&hist[bin], (unsigned)__popc(peers));
    }
    __syncthreads();
    {
        unsigned cnt = hist[t];
        unsigned v = cnt;
#pragma unroll
        for (int d = 1; d < 32; d <<= 1) {
            unsigned o = __shfl_up_sync(0xFFFFFFFFu, v, d);
            if (lane >= d) v += o;
        }
        if (lane == 31) wsum[t >> 5] = v;
        __syncthreads();
        unsigned woff = 0;
        for (int w = 0; w < (t >> 5); w++) woff += wsum[w];
        unsigned incl = v + woff;
        unsigned excl = incl - cnt;
        if (excl < KNN && incl >= KNN) { s_b1 = t; s_c1 = (int)excl; }
    }
    __syncthreads();
    unsigned b1 = (unsigned)s_b1;
    int c1 = s_c1;
    hist[t] = 0u;
    __syncthreads();
#pragma unroll
    for (int i = 0; i < 8; i++) {
        bool pred = (u[i] >> 24) == b1;
        unsigned act = __ballot_sync(0xFFFFFFFFu, pred);
        if (pred) {
            unsigned bin = (u[i] >> 16) & 255u;
            unsigned peers = __match_any_sync(act, bin);
            if ((peers & ((1u << lane) - 1u)) == 0u)
                atomicAdd(&hist[bin], (unsigned)__popc(peers));
        }
    }
    __syncthreads();
    int need2 = KNN - c1;
    {
        unsigned cnt = hist[t];
        unsigned v = cnt;
#pragma unroll
        for (int d = 1; d < 32; d <<= 1) {
            unsigned o = __shfl_up_sync(0xFFFFFFFFu, v, d);
            if (lane >= d) v += o;
        }
        if (lane == 31) wsum[t >> 5] = v;
        __syncthreads();
        unsigned woff = 0;
        for (int w = 0; w < (t >> 5); w++) woff += wsum[w];
        unsigned incl = v + woff;
        unsigned excl = incl - cnt;
        if ((int)excl < need2 && (int)incl >= need2) { s_b2 = t; s_c2 = (int)excl; }
    }
    __syncthreads();
    unsigned b2 = (unsigned)s_b2;
    int c2 = s_c2;
#pragma unroll
    for (int i = 0; i < 8; i++) {
        unsigned d1 = u[i] >> 24;
        if (d1 < b1) {
            out[atomicAdd(&s_sel, 1)] = t * 8 + i;
        } else if (d1 == b1) {
            unsigned d2 = (u[i] >> 16) & 255u;
            if (d2 < b2) {
                out[atomicAdd(&s_sel, 1)] = t * 8 + i;
            } else if (d2 == b2) {
                int c = atomicAdd(&s_cand, 1);
                if (c < CAND_MAX) { cand_u[c] = u[i]; cand_m[c] = t * 8 + i; }
            }
        }
    }
    __syncthreads();
    int need3 = need2 - c2;
    int cc2 = min(s_cand, CAND_MAX);
    for (int c = t; c < cc2; c += 256) {
        unsigned uc = cand_u[c];
        int mc = cand_m[c];
        int rank = 0;
        for (int j = 0; j < cc2; j++) {
            unsigned uj = cand_u[j];
            rank += (uj < uc || (uj == uc && cand_m[j] < mc)) ? 1 : 0;
        }
        if (rank < need3) out[atomicAdd(&s_sel, 1)] = mc;
    }
}

// P[b,n,:] = A^T x + bias ; Q[b,n,:] = C^T x  (pre-transposed weights, f32x2)
__global__ __launch_bounds__(256, 2) void k_pq(const float* __restrict__ x,
                                               const float* __restrict__ bias) {
    extern __shared__ float sm[];
    float* Ash = sm;                 // [64][128]
    float* Csh = sm + 8192;          // [64][128]
    float* xs  = sm + 16384;         // [64][64]
    int b  = blockIdx.y;
    int n0 = blockIdx.x * 64;
    int tid = threadIdx.x;
#pragma unroll
    for (int i = 0; i < 8; i++) {
        int id = (tid + 256 * i) * 4;
        *(float4*)(Ash + id) = *(const float4*)(g_A + id);
        *(float4*)(Csh + id) = *(const float4*)(g_C + id);
    }
#pragma unroll
    for (int i = 0; i < 4; i++) {
        int id = tid + 256 * i;
        int f = id >> 4, c = (id & 15) * 4;
        *(float4*)(xs + f * 64 + c) = *(const float4*)(x + ((size_t)b * FIN + f) * NP + n0 + c);
    }
    __syncthreads();
    int tn = tid & 7, to = tid >> 3;
    int o0 = to * 4, nl0 = tn * 8;
    u64 accP[4][4], accQ[4][4];
    float4 bi = *(const float4*)(bias + o0);
    float bia[4] = {bi.x, bi.y, bi.z, bi.w};
#pragma unroll
    for (int i = 0; i < 4; i++) {
        u64 bd = dupf(bia[i]);
#pragma unroll
        for (int j = 0; j < 4; j++) { accP[i][j] = bd; accQ[i][j] = 0ull; }
    }
#pragma unroll 4
    for (int f = 0; f < 64; f++) {
        float4 a4 = *(float4*)(Ash + f * 128 + o0);
        float4 c4 = *(float4*)(Csh + f * 128 + o0);
        ulonglong2 x0 = *(ulonglong2*)(xs + f * 64 + nl0);
        ulonglong2 x1 = *(ulonglong2*)(xs + f * 64 + nl0 + 4);
        u64 xp[4] = {x0.x, x0.y, x1.x, x1.y};
        float aa[4] = {a4.x, a4.y, a4.z, a4.w};
        float cc[4] = {c4.x, c4.y, c4.z, c4.w};
#pragma unroll
        for (int i = 0; i < 4; i++) {
            u64 ad = dupf(aa[i]), cd = dupf(cc[i]);
#pragma unroll
            for (int j = 0; j < 4; j++) {
                accP[i][j] = fma2(ad, xp[j], accP[i][j]);
                accQ[i][j] = fma2(cd, xp[j], accQ[i][j]);
            }
        }
    }
#pragma unroll
    for (int jj = 0; jj < 8; jj++) {
        int j = jj >> 1, h = jj & 1;
        float pv[4], qv[4];
#pragma unroll
        for (int i = 0; i < 4; i++) {
            float2 p2 = unpack2(accP[i][j]); pv[i] = h ? p2.y : p2.x;
            float2 q2 = unpack2(accQ[i][j]); qv[i] = h ? q2.y : q2.x;
        }
        size_t base = (size_t)(b * NP + n0 + nl0 + jj) * FOUT + o0;
        *(float4*)(g_P + base) = make_float4(pv[0], pv[1], pv[2], pv[3]);
        *(float4*)(g_Q + base) = make_float4(qv[0], qv[1], qv[2], qv[3]);
    }
}

// Per (b,n): gather K neighbor Q columns; ymax/ymin = P + max/min_k Q;
// accumulate per-channel sum(y), sum(y^2) over edges.
__global__ __launch_bounds__(256) void k_edge() {
    __shared__ float bs1[FOUT], bs2[FOUT];
    int tid = threadIdx.x;
    int w = tid >> 5, lane = tid & 31;
    if (tid < FOUT) { bs1[tid] = 0.f; bs2[tid] = 0.f; }
    __syncthreads();
    int gp = blockIdx.x * 8 + w;
    int b  = gp >> 11;
    size_t pbase = (size_t)gp * FOUT + lane * 4;
    float4 p = *(const float4*)(g_P + pbase);
    const int* idx = g_idx + gp * KNN;
    const float INF = __int_as_float(0x7f800000);
    float4 qmax = make_float4(-INF, -INF, -INF, -INF);
    float4 qmin = make_float4(INF, INF, INF, INF);
    float4 s  = make_float4(0.f, 0.f, 0.f, 0.f);
    float4 s2 = make_float4(0.f, 0.f, 0.f, 0.f);
#pragma unroll 4
    for (int k = 0; k < KNN; k++) {
        int m = __ldg(idx + k);
        float4 q = *(const float4*)(g_Q + ((size_t)(b * NP + m)) * FOUT + lane * 4);
        qmax.x = fmaxf(qmax.x, q.x); qmax.y = fmaxf(qmax.y, q.y);
        qmax.z = fmaxf(qmax.z, q.z); qmax.w = fmaxf(qmax.w, q.w);
        qmin.x = fminf(qmin.x, q.x); qmin.y = fminf(qmin.y, q.y);
        qmin.z = fminf(qmin.z, q.z); qmin.w = fminf(qmin.w, q.w);
        s.x += q.x; s.y += q.y; s.z += q.z; s.w += q.w;
        s2.x = fmaf(q.x, q.x, s2.x); s2.y = fmaf(q.y, q.y, s2.y);
        s2.z = fmaf(q.z, q.z, s2.z); s2.w = fmaf(q.w, q.w, s2.w);
    }
    float4 ymax = make_float4(p.x + qmax.x, p.y + qmax.y, p.z + qmax.z, p.w + qmax.w);
    float4 ymin = make_float4(p.x + qmin.x, p.y + qmin.y, p.z + qmin.z, p.w + qmin.w);
    *(float4*)(g_ymax + pbase) = ymax;
    *(float4*)(g_ymin + pbase) = ymin;
    float s1a[4], ssa[4];
    float pp[4] = {p.x, p.y, p.z, p.w};
    float sa[4] = {s.x, s.y, s.z, s.w};
    float s2a[4] = {s2.x, s2.y, s2.z, s2.w};
#pragma unroll
    for (int i = 0; i < 4; i++) {
        s1a[i] = fmaf((float)KNN, pp[i], sa[i]);
        ssa[i] = fmaf(pp[i], fmaf((float)KNN, pp[i], 2.f * sa[i]), s2a[i]);
    }
#pragma unroll
    for (int i = 0; i < 4; i++) {
        atomicAdd(&bs1[lane * 4 + i], s1a[i]);
        atomicAdd(&bs2[lane * 4 + i], ssa[i]);
    }
    __syncthreads();
    if (tid < FOUT) {
        atomicAdd(&g_S1[tid], bs1[tid]);
        atomicAdd(&g_S2[tid], bs2[tid]);
    }
}

__global__ void k_stats(const float* __restrict__ gamma, const float* __restrict__ beta) {
    int o = threadIdx.x;
    const float inv = 1.f / (float)EDGES;
    float m   = g_S1[o] * inv;
    float var = fmaf(-m, m, g_S2[o] * inv);
    float sc  = gamma[o] * rsqrtf(var + 1e-5f);
    g_scale[o] = sc;
    g_shift[o] = fmaf(-m, sc, beta[o]);
}

// out[b,o,n] = relu(scale*(scale>=0 ? ymax : ymin) + shift), transposed write.
__global__ __launch_bounds__(256) void k_out(float* __restrict__ out) {
    __shared__ float sh[FOUT * 36];
    __shared__ float ssc[FOUT], ssf[FOUT];
    int b  = blockIdx.y;
    int n0 = blockIdx.x * 32;
    int tid = threadIdx.x;
    if (tid < FOUT) { ssc[tid] = g_scale[tid]; ssf[tid] = g_shift[tid]; }
    __syncthreads();
    int o  = tid & 127;
    int nh = tid >> 7;
    float sc = ssc[o], sf = ssf[o];
#pragma unroll
    for (int it = 0; it < 16; it++) {
        int nl = it * 2 + nh;
        size_t base = ((size_t)(b * NP + n0 + nl)) * FOUT + o;
        float vmax = g_ymax[base], vmin = g_ymin[base];
        float v = (sc >= 0.f) ? vmax : vmin;
        sh[o * 36 + nl] = fmaxf(fmaf(sc, v, sf), 0.f);
    }
    __syncthreads();
    int ow = tid >> 1;
    int h  = tid & 1;
    float* dst = out + ((size_t)(b * FOUT + ow)) * NP + n0 + h * 16;
    const float* src = sh + ow * 36 + h * 16;
#pragma unroll
    for (int j = 0; j < 4; j++)
        *(float4*)(dst + j * 4) = *(const float4*)(src + j * 4);
}

// ---------------- launch ----------------------------------------------------
extern "C" void kernel_launch(void* const* d_in, const int* in_sizes, int n_in,
                              void* d_out, int out_size) {
    const float* x     = (const float*)d_in[0];
    const float* W     = (const float*)d_in[1];
    const float* bias  = (const float*)d_in[2];
    const float* gamma = (const float*)d_in[3];
    const float* beta  = (const float*)d_in[4];
    float* out = (float*)d_out;

    const int GRAM_SMEM = 256 * 65 * 4;   // 66560 B
    const int PQ_SMEM   = (2 * 64 * 128 + 64 * 64) * 4;  // 81920 B
    cudaFuncSetAttribute(k_gram, cudaFuncAttributeMaxDynamicSharedMemorySize, GRAM_SMEM);
    cudaFuncSetAttribute(k_pq,   cudaFuncAttributeMaxDynamicSharedMemorySize, PQ_SMEM);

    k_zero<<<1, 128>>>();
    k_prep<<<32, 256>>>(W);
    k_sq<<<NPTS / 256, 256>>>(x);
    k_gram<<<dim3(136, 1, NB), 256, GRAM_SMEM>>>(x);
    k_select<<<NPTS, 256>>>();
    k_pq<<<dim3(NP / 64, NB), 256, PQ_SMEM>>>(x, bias);
    k_edge<<<NPTS / 8, 256>>>();
    k_stats<<<1, 128>>>(gamma, beta);
    k_out<<<dim3(NP / 32, NB), 256>>>(out);
}

// round 13
// speedup vs baseline: 1.3440x; 1.3440x over previous
#include <cuda_runtime.h>
#include <cstdint>

#define NB   16
#define FIN  64
#define FOUT 128
#define NP   2048
#define KNN  20
#define NPTS (NB * NP)            /* 32768 */
#define EDGES (NPTS * KNN)        /* 655360 */

typedef unsigned long long u64;

// ---------------- scratch (device globals: no allocations allowed) ----------
__device__ float          g_sq[NPTS];
__device__ unsigned short g_pre[(size_t)NPTS * NP];   // 128 MB: 16-bit sortable key prefixes
__device__ int            g_idx[NPTS * KNN];
__device__ float          g_A[FIN * FOUT];            // (W1-W2)^T  [f][o]
__device__ float          g_C[FIN * FOUT];            // W2^T       [f][o]
__device__ float          g_P[NPTS * FOUT];
__device__ float          g_Q[NPTS * FOUT];
__device__ float          g_ymax[NPTS * FOUT];
__device__ float          g_ymin[NPTS * FOUT];
__device__ float          g_S1[FOUT];
__device__ float          g_S2[FOUT];
__device__ float          g_scale[FOUT];
__device__ float          g_shift[FOUT];

// ---------------- f32x2 helpers (Blackwell packed fp32 FMA) -----------------
__device__ __forceinline__ u64 fma2(u64 a, u64 b, u64 c) {
    u64 d;
    asm("fma.rn.f32x2 %0, %1, %2, %3;" : "=l"(d) : "l"(a), "l"(b), "l"(c));
    return d;
}
__device__ __forceinline__ u64 dupf(float a) {
    u64 d;
    unsigned u = __float_as_uint(a);
    asm("mov.b64 %0, {%1, %1};" : "=l"(d) : "r"(u));
    return d;
}
__device__ __forceinline__ float2 unpack2(u64 d) {
    unsigned lo, hi;
    asm("mov.b64 {%0, %1}, %2;" : "=r"(lo), "=r"(hi) : "l"(d));
    return make_float2(__uint_as_float(lo), __uint_as_float(hi));
}
// monotone float -> unsigned-sortable transform
__device__ __forceinline__ unsigned tkey(float f) {
    unsigned b = __float_as_uint(f);
    return ((int)b < 0) ? ~b : (b | 0x80000000u);
}

// ---------------- kernels ---------------------------------------------------

__global__ void k_zero() {
    int t = threadIdx.x;
    if (t < FOUT) { g_S1[t] = 0.f; g_S2[t] = 0.f; }
}

// sq[b,n] = sum_f x^2
__global__ void k_sq(const float* __restrict__ x) {
    int gp = blockIdx.x * blockDim.x + threadIdx.x;
    if (gp >= NPTS) return;
    int b = gp >> 11, n = gp & (NP - 1);
    const float* p = x + (size_t)b * FIN * NP + n;
    float s = 0.f;
#pragma unroll
    for (int f = 0; f < FIN; f++) { float v = p[(size_t)f * NP]; s = fmaf(v, v, s); }
    g_sq[gp] = s;
}

// Transpose weights: g_A[f][o] = W[o][f]-W[o][64+f], g_C[f][o] = W[o][64+f]
__global__ void k_prep(const float* __restrict__ W) {
    int id = blockIdx.x * 256 + threadIdx.x;   // 0..8191
    if (id >= FIN * FOUT) return;
    int f = id >> 7, o = id & 127;
    float w1 = W[o * 128 + f], w2 = W[o * 128 + 64 + f];
    g_A[f * 128 + o] = w1 - w2;
    g_C[f * 128 + o] = w2;
}

// Symmetric Gram, lower-triangle 128x128 tiles. Stores ONLY the 16-bit
// sortable prefix of key = sq[m]-2G (half the DRAM bytes of full keys);
// k_select's two radix rounds consume exactly these 16 bits, and boundary
// candidates are re-ranked from exact recomputed distances.
__global__ __launch_bounds__(256, 2) void k_gram(const float* __restrict__ x) {
    extern __shared__ float sm[];
    float* As = sm;               // [64][128]
    float* Bs = sm + 64 * 128;    // [64][128]
    int b = blockIdx.z;
    int kk = blockIdx.x;
    int ti = (int)((sqrtf(8.f * kk + 1.f) - 1.f) * 0.5f);
    while ((ti + 1) * (ti + 2) / 2 <= kk) ti++;
    while (ti * (ti + 1) / 2 > kk) ti--;
    int tj = kk - ti * (ti + 1) / 2;
    int n0 = ti * 128;            // rows
    int m0 = tj * 128;            // cols
    int tid = threadIdx.x;
    const float* xb = x + (size_t)b * FIN * NP;
#pragma unroll
    for (int i = 0; i < 8; i++) {
        int flat = (tid + 256 * i) * 4;
        int k = flat >> 7;
        int c = flat & 127;
        *(float4*)(As + k * 128 + c) = *(const float4*)(xb + (size_t)k * NP + n0 + c);
        *(float4*)(Bs + k * 128 + c) = *(const float4*)(xb + (size_t)k * NP + m0 + c);
    }
    __syncthreads();
    int tx = tid & 15, ty = tid >> 4;
    u64 acc[8][4];
#pragma unroll
    for (int i = 0; i < 8; i++)
#pragma unroll
        for (int j = 0; j < 4; j++) acc[i][j] = 0ull;

#pragma unroll 4
    for (int k = 0; k < 64; k++) {
        float4 a0 = *(float4*)(As + k * 128 + ty * 8);
        float4 a1 = *(float4*)(As + k * 128 + ty * 8 + 4);
        ulonglong2 bv0 = *(ulonglong2*)(Bs + k * 128 + tx * 8);
        ulonglong2 bv1 = *(ulonglong2*)(Bs + k * 128 + tx * 8 + 4);
        float av[8] = {a0.x, a0.y, a0.z, a0.w, a1.x, a1.y, a1.z, a1.w};
        u64 bv[4] = {bv0.x, bv0.y, bv1.x, bv1.y};
#pragma unroll
        for (int i = 0; i < 8; i++) {
            u64 ad = dupf(av[i]);
#pragma unroll
            for (int j = 0; j < 4; j++) acc[i][j] = fma2(ad, bv[j], acc[i][j]);
        }
    }
    float gf[8][8];
#pragma unroll
    for (int i = 0; i < 8; i++)
#pragma unroll
        for (int j = 0; j < 4; j++) {
            float2 p = unpack2(acc[i][j]);
            gf[i][2 * j] = p.x; gf[i][2 * j + 1] = p.y;
        }
    // direct tile: rows n0+ty*8+i, cols m0+tx*8+k
    {
        float sqm[8];
        *(float4*)sqm       = *(const float4*)(g_sq + b * NP + m0 + tx * 8);
        *(float4*)(sqm + 4) = *(const float4*)(g_sq + b * NP + m0 + tx * 8 + 4);
#pragma unroll
        for (int i = 0; i < 8; i++) {
            unsigned q[4];
#pragma unroll
            for (int j = 0; j < 4; j++) {
                unsigned lo = tkey(fmaf(gf[i][2 * j],     -2.f, sqm[2 * j]))     >> 16;
                unsigned hi = tkey(fmaf(gf[i][2 * j + 1], -2.f, sqm[2 * j + 1])) >> 16;
                q[j] = lo | (hi << 16);
            }
            unsigned short* op = g_pre + ((size_t)(b * NP + n0 + ty * 8 + i)) * NP + m0 + tx * 8;
            *(uint4*)op = make_uint4(q[0], q[1], q[2], q[3]);
        }
    }
    // transposed tile (off-diagonal only): rows m0+ty*8+r, cols n0+tx*8+c
    if (ti != tj) {
        __syncthreads();
        int s = tid;
        float* slots = sm;
#pragma unroll
        for (int k = 0; k < 8; k++)
#pragma unroll
            for (int i = 0; i < 8; i++)
                slots[s * 65 + k * 8 + ((i + s) & 7)] = gf[i][k];
        __syncthreads();
        int s2 = ((tid & 15) << 4) | (tid >> 4);
        float sqn[8];
        *(float4*)sqn       = *(const float4*)(g_sq + b * NP + n0 + tx * 8);
        *(float4*)(sqn + 4) = *(const float4*)(g_sq + b * NP + n0 + tx * 8 + 4);
#pragma unroll
        for (int r = 0; r < 8; r++) {
            unsigned q[4];
#pragma unroll
            for (int j = 0; j < 4; j++) {
                float w0 = slots[s2 * 65 + r * 8 + ((2 * j + s2) & 7)];
                float w1 = slots[s2 * 65 + r * 8 + ((2 * j + 1 + s2) & 7)];
                unsigned lo = tkey(fmaf(w0, -2.f, sqn[2 * j]))     >> 16;
                unsigned hi = tkey(fmaf(w1, -2.f, sqn[2 * j + 1])) >> 16;
                q[j] = lo | (hi << 16);
            }
            unsigned short* op = g_pre + ((size_t)(b * NP + m0 + ty * 8 + r)) * NP + n0 + tx * 8;
            *(uint4*)op = make_uint4(q[0], q[1], q[2], q[3]);
        }
    }
}

// Two-round 8-bit radix on 16-bit prefixes (R11 structure verbatim). After
// round 2 the bin IS the exact boundary prefix B. Keys with prefix < B are
// selected outright; prefix == B candidates (~3-10) are re-ranked by exact
// recomputed distance (x is L2-hot; 64-FMA dot per candidate).
#define CAND_MAX 128
__global__ __launch_bounds__(256) void k_select(const float* __restrict__ x) {
    int gp = blockIdx.x;                       // b*NP + n
    int n  = gp & (NP - 1);
    int b  = gp >> 11;
    const uint4* row4 = (const uint4*)(g_pre + (size_t)gp * NP);
    __shared__ unsigned hist[256];
    __shared__ int  cand_m[CAND_MAX];
    __shared__ u64  cand_k[CAND_MAX];
    __shared__ unsigned wsum[8];
    __shared__ int s_sel, s_cand, s_b1, s_c1, s_b2, s_c2;
    int t = threadIdx.x;
    int lane = t & 31;
    hist[t] = 0u;
    if (t == 0) { s_sel = 0; s_cand = 0; }
    __syncthreads();

    unsigned p[8];
    {
        uint4 a = __ldcs(row4 + t);
        p[0] = a.x & 0xFFFFu; p[1] = a.x >> 16;
        p[2] = a.y & 0xFFFFu; p[3] = a.y >> 16;
        p[4] = a.z & 0xFFFFu; p[5] = a.z >> 16;
        p[6] = a.w & 0xFFFFu; p[7] = a.w >> 16;
        int d = n - t * 8;
        if (d >= 0 && d < 8) p[d] = 0xFFFFu;   // exclude self
    }
    // round-1 histogram on prefix bits [15:8], warp-aggregated
#pragma unroll
    for (int i = 0; i < 8; i++) {
        unsigned bin = p[i] >> 8;
        unsigned peers = __match_any_sync(0xFFFFFFFFu, bin);
        if ((peers & ((1u << lane) - 1u)) == 0u)
            atomicAdd(&hist[bin], (unsigned)__popc(peers));
    }
    __syncthreads();
    // scan 1
    {
        unsigned cnt = hist[t];
        unsigned v = cnt;
#pragma unroll
        for (int d = 1; d < 32; d <<= 1) {
            unsigned o = __shfl_up_sync(0xFFFFFFFFu, v, d);
            if (lane >= d) v += o;
        }
        if (lane == 31) wsum[t >> 5] = v;
        __syncthreads();
        unsigned woff = 0;
        for (int w = 0; w < (t >> 5); w++) woff += wsum[w];
        unsigned incl = v + woff;
        unsigned excl = incl - cnt;
        if (excl < KNN && incl >= KNN) { s_b1 = t; s_c1 = (int)excl; }
    }
    __syncthreads();
    unsigned b1 = (unsigned)s_b1;
    int c1 = s_c1;
    hist[t] = 0u;
    __syncthreads();
    // round-2 histogram on prefix bits [7:0] within bin b1
#pragma unroll
    for (int i = 0; i < 8; i++) {
        bool pred = (p[i] >> 8) == b1;
        unsigned act = __ballot_sync(0xFFFFFFFFu, pred);
        if (pred) {
            unsigned bin = p[i] & 255u;
            unsigned peers = __match_any_sync(act, bin);
            if ((peers & ((1u << lane) - 1u)) == 0u)
                atomicAdd(&hist[bin], (unsigned)__popc(peers));
        }
    }
    __syncthreads();
    int need2 = KNN - c1;
    // scan 2
    {
        unsigned cnt = hist[t];
        unsigned v = cnt;
#pragma unroll
        for (int d = 1; d < 32; d <<= 1) {
            unsigned o = __shfl_up_sync(0xFFFFFFFFu, v, d);
            if (lane >= d) v += o;
        }
        if (lane == 31) wsum[t >> 5] = v;
        __syncthreads();
        unsigned woff = 0;
        for (int w = 0; w < (t >> 5); w++) woff += wsum[w];
        unsigned incl = v + woff;
        unsigned excl = incl - cnt;
        if ((int)excl < need2 && (int)incl >= need2) { s_b2 = t; s_c2 = (int)excl; }
    }
    __syncthreads();
    unsigned B = (b1 << 8) | (unsigned)s_b2;   // exact boundary prefix
    int c2 = s_c2;
    int need3 = need2 - c2;                    // take need3 from prefix == B
    int* out = g_idx + gp * KNN;
#pragma unroll
    for (int i = 0; i < 8; i++) {
        if (p[i] < B) {
            out[atomicAdd(&s_sel, 1)] = t * 8 + i;
        } else if (p[i] == B) {
            int c = atomicAdd(&s_cand, 1);
            if (c < CAND_MAX) cand_m[c] = t * 8 + i;
        }
    }
    __syncthreads();
    if (need3 <= 0) return;
    int cb = min(s_cand, CAND_MAX);
    // recompute exact keys for boundary candidates (x is L2-resident)
    u64 myk = 0;
    if (t < cb) {
        int m = cand_m[t];
        const float* xn = x + (size_t)b * FIN * NP + n;
        const float* xm = x + (size_t)b * FIN * NP + m;
        float dot = 0.f;
#pragma unroll
        for (int f = 0; f < FIN; f++)
            dot = fmaf(xn[(size_t)f * NP], xm[(size_t)f * NP], dot);
        float v = fmaf(dot, -2.f, g_sq[b * NP + m]);
        myk = (((u64)tkey(v)) << 32) | (unsigned)m;
        cand_k[t] = myk;
    }
    __syncthreads();
    if (t < cb) {
        int rank = 0;
        for (int j = 0; j < cb; j++)
            rank += (cand_k[j] < myk) ? 1 : 0;
        if (rank < need3) out[atomicAdd(&s_sel, 1)] = cand_m[t];
    }
}

// P[b,n,:] = A^T x + bias ; Q[b,n,:] = C^T x  (pre-transposed weights, f32x2)
__global__ __launch_bounds__(256, 2) void k_pq(const float* __restrict__ x,
                                               const float* __restrict__ bias) {
    extern __shared__ float sm[];
    float* Ash = sm;                 // [64][128]
    float* Csh = sm + 8192;          // [64][128]
    float* xs  = sm + 16384;         // [64][64]
    int b  = blockIdx.y;
    int n0 = blockIdx.x * 64;
    int tid = threadIdx.x;
#pragma unroll
    for (int i = 0; i < 8; i++) {
        int id = (tid + 256 * i) * 4;
        *(float4*)(Ash + id) = *(const float4*)(g_A + id);
        *(float4*)(Csh + id) = *(const float4*)(g_C + id);
    }
#pragma unroll
    for (int i = 0; i < 4; i++) {
        int id = tid + 256 * i;
        int f = id >> 4, c = (id & 15) * 4;
        *(float4*)(xs + f * 64 + c) = *(const float4*)(x + ((size_t)b * FIN + f) * NP + n0 + c);
    }
    __syncthreads();
    int tn = tid & 7, to = tid >> 3;
    int o0 = to * 4, nl0 = tn * 8;
    u64 accP[4][4], accQ[4][4];
    float4 bi = *(const float4*)(bias + o0);
    float bia[4] = {bi.x, bi.y, bi.z, bi.w};
#pragma unroll
    for (int i = 0; i < 4; i++) {
        u64 bd = dupf(bia[i]);
#pragma unroll
        for (int j = 0; j < 4; j++) { accP[i][j] = bd; accQ[i][j] = 0ull; }
    }
#pragma unroll 4
    for (int f = 0; f < 64; f++) {
        float4 a4 = *(float4*)(Ash + f * 128 + o0);
        float4 c4 = *(float4*)(Csh + f * 128 + o0);
        ulonglong2 x0 = *(ulonglong2*)(xs + f * 64 + nl0);
        ulonglong2 x1 = *(ulonglong2*)(xs + f * 64 + nl0 + 4);
        u64 xp[4] = {x0.x, x0.y, x1.x, x1.y};
        float aa[4] = {a4.x, a4.y, a4.z, a4.w};
        float cc[4] = {c4.x, c4.y, c4.z, c4.w};
#pragma unroll
        for (int i = 0; i < 4; i++) {
            u64 ad = dupf(aa[i]), cd = dupf(cc[i]);
#pragma unroll
            for (int j = 0; j < 4; j++) {
                accP[i][j] = fma2(ad, xp[j], accP[i][j]);
                accQ[i][j] = fma2(cd, xp[j], accQ[i][j]);
            }
        }
    }
#pragma unroll
    for (int jj = 0; jj < 8; jj++) {
        int j = jj >> 1, h = jj & 1;
        float pv[4], qv[4];
#pragma unroll
        for (int i = 0; i < 4; i++) {
            float2 p2 = unpack2(accP[i][j]); pv[i] = h ? p2.y : p2.x;
            float2 q2 = unpack2(accQ[i][j]); qv[i] = h ? q2.y : q2.x;
        }
        size_t base = (size_t)(b * NP + n0 + nl0 + jj) * FOUT + o0;
        *(float4*)(g_P + base) = make_float4(pv[0], pv[1], pv[2], pv[3]);
        *(float4*)(g_Q + base) = make_float4(qv[0], qv[1], qv[2], qv[3]);
    }
}

// Per (b,n): gather K neighbor Q columns; ymax/ymin = P + max/min_k Q;
// accumulate per-channel sum(y), sum(y^2) over edges.
__global__ __launch_bounds__(256) void k_edge() {
    __shared__ float bs1[FOUT], bs2[FOUT];
    int tid = threadIdx.x;
    int w = tid >> 5, lane = tid & 31;
    if (tid < FOUT) { bs1[tid] = 0.f; bs2[tid] = 0.f; }
    __syncthreads();
    int gp = blockIdx.x * 8 + w;
    int b  = gp >> 11;
    size_t pbase = (size_t)gp * FOUT + lane * 4;
    float4 p = *(const float4*)(g_P + pbase);
    const int* idx = g_idx + gp * KNN;
    const float INF = __int_as_float(0x7f800000);
    float4 qmax = make_float4(-INF, -INF, -INF, -INF);
    float4 qmin = make_float4(INF, INF, INF, INF);
    float4 s  = make_float4(0.f, 0.f, 0.f, 0.f);
    float4 s2 = make_float4(0.f, 0.f, 0.f, 0.f);
#pragma unroll 4
    for (int k = 0; k < KNN; k++) {
        int m = __ldg(idx + k);
        float4 q = *(const float4*)(g_Q + ((size_t)(b * NP + m)) * FOUT + lane * 4);
        qmax.x = fmaxf(qmax.x, q.x); qmax.y = fmaxf(qmax.y, q.y);
        qmax.z = fmaxf(qmax.z, q.z); qmax.w = fmaxf(qmax.w, q.w);
        qmin.x = fminf(qmin.x, q.x); qmin.y = fminf(qmin.y, q.y);
        qmin.z = fminf(qmin.z, q.z); qmin.w = fminf(qmin.w, q.w);
        s.x += q.x; s.y += q.y; s.z += q.z; s.w += q.w;
        s2.x = fmaf(q.x, q.x, s2.x); s2.y = fmaf(q.y, q.y, s2.y);
        s2.z = fmaf(q.z, q.z, s2.z); s2.w = fmaf(q.w, q.w, s2.w);
    }
    float4 ymax = make_float4(p.x + qmax.x, p.y + qmax.y, p.z + qmax.z, p.w + qmax.w);
    float4 ymin = make_float4(p.x + qmin.x, p.y + qmin.y, p.z + qmin.z, p.w + qmin.w);
    *(float4*)(g_ymax + pbase) = ymax;
    *(float4*)(g_ymin + pbase) = ymin;
    float s1a[4], ssa[4];
    float pp[4] = {p.x, p.y, p.z, p.w};
    float sa[4] = {s.x, s.y, s.z, s.w};
    float s2a[4] = {s2.x, s2.y, s2.z, s2.w};
#pragma unroll
    for (int i = 0; i < 4; i++) {
        s1a[i] = fmaf((float)KNN, pp[i], sa[i]);
        ssa[i] = fmaf(pp[i], fmaf((float)KNN, pp[i], 2.f * sa[i]), s2a[i]);
    }
#pragma unroll
    for (int i = 0; i < 4; i++) {
        atomicAdd(&bs1[lane * 4 + i], s1a[i]);
        atomicAdd(&bs2[lane * 4 + i], ssa[i]);
    }
    __syncthreads();
    if (tid < FOUT) {
        atomicAdd(&g_S1[tid], bs1[tid]);
        atomicAdd(&g_S2[tid], bs2[tid]);
    }
}

__global__ void k_stats(const float* __restrict__ gamma, const float* __restrict__ beta) {
    int o = threadIdx.x;
    const float inv = 1.f / (float)EDGES;
    float m   = g_S1[o] * inv;
    float var = fmaf(-m, m, g_S2[o] * inv);
    float sc  = gamma[o] * rsqrtf(var + 1e-5f);
    g_scale[o] = sc;
    g_shift[o] = fmaf(-m, sc, beta[o]);
}

// out[b,o,n] = relu(scale*(scale>=0 ? ymax : ymin) + shift), transposed write.
__global__ __launch_bounds__(256) void k_out(float* __restrict__ out) {
    __shared__ float sh[FOUT * 36];
    __shared__ float ssc[FOUT], ssf[FOUT];
    int b  = blockIdx.y;
    int n0 = blockIdx.x * 32;
    int tid = threadIdx.x;
    if (tid < FOUT) { ssc[tid] = g_scale[tid]; ssf[tid] = g_shift[tid]; }
    __syncthreads();
    int o  = tid & 127;
    int nh = tid >> 7;
    float sc = ssc[o], sf = ssf[o];
#pragma unroll
    for (int it = 0; it < 16; it++) {
        int nl = it * 2 + nh;
        size_t base = ((size_t)(b * NP + n0 + nl)) * FOUT + o;
        float vmax = g_ymax[base], vmin = g_ymin[base];
        float v = (sc >= 0.f) ? vmax : vmin;
        sh[o * 36 + nl] = fmaxf(fmaf(sc, v, sf), 0.f);
    }
    __syncthreads();
    int ow = tid >> 1;
    int h  = tid & 1;
    float* dst = out + ((size_t)(b * FOUT + ow)) * NP + n0 + h * 16;
    const float* src = sh + ow * 36 + h * 16;
#pragma unroll
    for (int j = 0; j < 4; j++)
        *(float4*)(dst + j * 4) = *(const float4*)(src + j * 4);
}

// ---------------- launch ----------------------------------------------------
extern "C" void kernel_launch(void* const* d_in, const int* in_sizes, int n_in,
                              void* d_out, int out_size) {
    const float* x     = (const float*)d_in[0];
    const float* W     = (const float*)d_in[1];
    const float* bias  = (const float*)d_in[2];
    const float* gamma = (const float*)d_in[3];
    const float* beta  = (const float*)d_in[4];
    float* out = (float*)d_out;

    const int GRAM_SMEM = 256 * 65 * 4;   // 66560 B
    const int PQ_SMEM   = (2 * 64 * 128 + 64 * 64) * 4;  // 81920 B
    cudaFuncSetAttribute(k_gram, cudaFuncAttributeMaxDynamicSharedMemorySize, GRAM_SMEM);
    cudaFuncSetAttribute(k_pq,   cudaFuncAttributeMaxDynamicSharedMemorySize, PQ_SMEM);

    k_zero<<<1, 128>>>();
    k_prep<<<32, 256>>>(W);
    k_sq<<<NPTS / 256, 256>>>(x);
    k_gram<<<dim3(136, 1, NB), 256, GRAM_SMEM>>>(x);
    k_select<<<NPTS, 256>>>(x);
    k_pq<<<dim3(NP / 64, NB), 256, PQ_SMEM>>>(x, bias);
    k_edge<<<NPTS / 8, 256>>>();
    k_stats<<<1, 128>>>(gamma, beta);
    k_out<<<dim3(NP / 32, NB), 256>>>(out);
}

// round 14
// speedup vs baseline: 1.3500x; 1.0045x over previous
#include <cuda_runtime.h>
#include <cstdint>

#define NB   16
#define FIN  64
#define FOUT 128
#define NP   2048
#define KNN  20
#define NPTS (NB * NP)            /* 32768 */
#define EDGES (NPTS * KNN)        /* 655360 */

typedef unsigned long long u64;

// ---------------- scratch (device globals: no allocations allowed) ----------
__device__ float          g_sq[NPTS];
__device__ float          g_xt[(size_t)NPTS * FIN];  // 8 MB point-major copy of x
__device__ unsigned short g_pre[(size_t)NPTS * NP];  // 128 MB: 16-bit sortable key prefixes
__device__ int            g_idx[NPTS * KNN];
__device__ float          g_A[FIN * FOUT];           // (W1-W2)^T  [f][o]
__device__ float          g_C[FIN * FOUT];           // W2^T       [f][o]
__device__ float          g_P[NPTS * FOUT];
__device__ float          g_Q[NPTS * FOUT];
__device__ float          g_ymax[NPTS * FOUT];
__device__ float          g_ymin[NPTS * FOUT];
__device__ float          g_S1[FOUT];
__device__ float          g_S2[FOUT];
__device__ float          g_scale[FOUT];
__device__ float          g_shift[FOUT];

// ---------------- f32x2 helpers (Blackwell packed fp32 FMA) -----------------
__device__ __forceinline__ u64 fma2(u64 a, u64 b, u64 c) {
    u64 d;
    asm("fma.rn.f32x2 %0, %1, %2, %3;" : "=l"(d) : "l"(a), "l"(b), "l"(c));
    return d;
}
__device__ __forceinline__ u64 dupf(float a) {
    u64 d;
    unsigned u = __float_as_uint(a);
    asm("mov.b64 %0, {%1, %1};" : "=l"(d) : "r"(u));
    return d;
}
__device__ __forceinline__ float2 unpack2(u64 d) {
    unsigned lo, hi;
    asm("mov.b64 {%0, %1}, %2;" : "=r"(lo), "=r"(hi) : "l"(d));
    return make_float2(__uint_as_float(lo), __uint_as_float(hi));
}
// monotone float -> unsigned-sortable transform
__device__ __forceinline__ unsigned tkey(float f) {
    unsigned b = __float_as_uint(f);
    return ((int)b < 0) ? ~b : (b | 0x80000000u);
}

// ---------------- kernels ---------------------------------------------------

__global__ void k_zero() {
    int t = threadIdx.x;
    if (t < FOUT) { g_S1[t] = 0.f; g_S2[t] = 0.f; }
}

// sq[b,n] = sum_f x^2 ; also emit point-major transposed copy g_xt[n][f]
__global__ void k_sq(const float* __restrict__ x) {
    int gp = blockIdx.x * blockDim.x + threadIdx.x;
    if (gp >= NPTS) return;
    int b = gp >> 11, n = gp & (NP - 1);
    const float* p = x + (size_t)b * FIN * NP + n;
    float* xt = g_xt + (size_t)gp * FIN;
    float s = 0.f;
#pragma unroll
    for (int f = 0; f < FIN; f++) {
        float v = p[(size_t)f * NP];
        xt[f] = v;
        s = fmaf(v, v, s);
    }
    g_sq[gp] = s;
}

// Transpose weights: g_A[f][o] = W[o][f]-W[o][64+f], g_C[f][o] = W[o][64+f]
__global__ void k_prep(const float* __restrict__ W) {
    int id = blockIdx.x * 256 + threadIdx.x;   // 0..8191
    if (id >= FIN * FOUT) return;
    int f = id >> 7, o = id & 127;
    float w1 = W[o * 128 + f], w2 = W[o * 128 + 64 + f];
    g_A[f * 128 + o] = w1 - w2;
    g_C[f * 128 + o] = w2;
}

// Symmetric Gram, lower-triangle 128x128 tiles. Stores ONLY the 16-bit
// sortable prefix of key = sq[m]-2G (half the DRAM bytes of full keys).
__global__ __launch_bounds__(256, 2) void k_gram(const float* __restrict__ x) {
    extern __shared__ float sm[];
    float* As = sm;               // [64][128]
    float* Bs = sm + 64 * 128;    // [64][128]
    int b = blockIdx.z;
    int kk = blockIdx.x;
    int ti = (int)((sqrtf(8.f * kk + 1.f) - 1.f) * 0.5f);
    while ((ti + 1) * (ti + 2) / 2 <= kk) ti++;
    while (ti * (ti + 1) / 2 > kk) ti--;
    int tj = kk - ti * (ti + 1) / 2;
    int n0 = ti * 128;            // rows
    int m0 = tj * 128;            // cols
    int tid = threadIdx.x;
    const float* xb = x + (size_t)b * FIN * NP;
#pragma unroll
    for (int i = 0; i < 8; i++) {
        int flat = (tid + 256 * i) * 4;
        int k = flat >> 7;
        int c = flat & 127;
        *(float4*)(As + k * 128 + c) = *(const float4*)(xb + (size_t)k * NP + n0 + c);
        *(float4*)(Bs + k * 128 + c) = *(const float4*)(xb + (size_t)k * NP + m0 + c);
    }
    __syncthreads();
    int tx = tid & 15, ty = tid >> 4;
    u64 acc[8][4];
#pragma unroll
    for (int i = 0; i < 8; i++)
#pragma unroll
        for (int j = 0; j < 4; j++) acc[i][j] = 0ull;

#pragma unroll 4
    for (int k = 0; k < 64; k++) {
        float4 a0 = *(float4*)(As + k * 128 + ty * 8);
        float4 a1 = *(float4*)(As + k * 128 + ty * 8 + 4);
        ulonglong2 bv0 = *(ulonglong2*)(Bs + k * 128 + tx * 8);
        ulonglong2 bv1 = *(ulonglong2*)(Bs + k * 128 + tx * 8 + 4);
        float av[8] = {a0.x, a0.y, a0.z, a0.w, a1.x, a1.y, a1.z, a1.w};
        u64 bv[4] = {bv0.x, bv0.y, bv1.x, bv1.y};
#pragma unroll
        for (int i = 0; i < 8; i++) {
            u64 ad = dupf(av[i]);
#pragma unroll
            for (int j = 0; j < 4; j++) acc[i][j] = fma2(ad, bv[j], acc[i][j]);
        }
    }
    float gf[8][8];
#pragma unroll
    for (int i = 0; i < 8; i++)
#pragma unroll
        for (int j = 0; j < 4; j++) {
            float2 p = unpack2(acc[i][j]);
            gf[i][2 * j] = p.x; gf[i][2 * j + 1] = p.y;
        }
    // direct tile: rows n0+ty*8+i, cols m0+tx*8+k
    {
        float sqm[8];
        *(float4*)sqm       = *(const float4*)(g_sq + b * NP + m0 + tx * 8);
        *(float4*)(sqm + 4) = *(const float4*)(g_sq + b * NP + m0 + tx * 8 + 4);
#pragma unroll
        for (int i = 0; i < 8; i++) {
            unsigned q[4];
#pragma unroll
            for (int j = 0; j < 4; j++) {
                unsigned lo = tkey(fmaf(gf[i][2 * j],     -2.f, sqm[2 * j]))     >> 16;
                unsigned hi = tkey(fmaf(gf[i][2 * j + 1], -2.f, sqm[2 * j + 1])) >> 16;
                q[j] = lo | (hi << 16);
            }
            unsigned short* op = g_pre + ((size_t)(b * NP + n0 + ty * 8 + i)) * NP + m0 + tx * 8;
            *(uint4*)op = make_uint4(q[0], q[1], q[2], q[3]);
        }
    }
    // transposed tile (off-diagonal only): rows m0+ty*8+r, cols n0+tx*8+c
    if (ti != tj) {
        __syncthreads();
        int s = tid;
        float* slots = sm;
#pragma unroll
        for (int k = 0; k < 8; k++)
#pragma unroll
            for (int i = 0; i < 8; i++)
                slots[s * 65 + k * 8 + ((i + s) & 7)] = gf[i][k];
        __syncthreads();
        int s2 = ((tid & 15) << 4) | (tid >> 4);
        float sqn[8];
        *(float4*)sqn       = *(const float4*)(g_sq + b * NP + n0 + tx * 8);
        *(float4*)(sqn + 4) = *(const float4*)(g_sq + b * NP + n0 + tx * 8 + 4);
#pragma unroll
        for (int r = 0; r < 8; r++) {
            unsigned q[4];
#pragma unroll
            for (int j = 0; j < 4; j++) {
                float w0 = slots[s2 * 65 + r * 8 + ((2 * j + s2) & 7)];
                float w1 = slots[s2 * 65 + r * 8 + ((2 * j + 1 + s2) & 7)];
                unsigned lo = tkey(fmaf(w0, -2.f, sqn[2 * j]))     >> 16;
                unsigned hi = tkey(fmaf(w1, -2.f, sqn[2 * j + 1])) >> 16;
                q[j] = lo | (hi << 16);
            }
            unsigned short* op = g_pre + ((size_t)(b * NP + m0 + ty * 8 + r)) * NP + n0 + tx * 8;
            *(uint4*)op = make_uint4(q[0], q[1], q[2], q[3]);
        }
    }
}

// Two-round 8-bit radix on 16-bit prefixes. After round 2 the bin IS the
// exact boundary prefix B. prefix < B selected outright; prefix == B
// candidates re-ranked by exact distance recomputed from point-major g_xt
// (contiguous 64-float rows -> 4 cache lines, no strided latency chain).
#define CAND_MAX 128
__global__ __launch_bounds__(256) void k_select() {
    int gp = blockIdx.x;                       // b*NP + n
    int n  = gp & (NP - 1);
    int b  = gp >> 11;
    const uint4* row4 = (const uint4*)(g_pre + (size_t)gp * NP);
    __shared__ unsigned hist[256];
    __shared__ int  cand_m[CAND_MAX];
    __shared__ u64  cand_k[CAND_MAX];
    __shared__ unsigned wsum[8];
    __shared__ int s_sel, s_cand, s_b1, s_c1, s_b2, s_c2;
    int t = threadIdx.x;
    int lane = t & 31;
    hist[t] = 0u;
    if (t == 0) { s_sel = 0; s_cand = 0; }
    __syncthreads();

    unsigned p[8];
    {
        uint4 a = __ldcs(row4 + t);
        p[0] = a.x & 0xFFFFu; p[1] = a.x >> 16;
        p[2] = a.y & 0xFFFFu; p[3] = a.y >> 16;
        p[4] = a.z & 0xFFFFu; p[5] = a.z >> 16;
        p[6] = a.w & 0xFFFFu; p[7] = a.w >> 16;
        int d = n - t * 8;
        if (d >= 0 && d < 8) p[d] = 0xFFFFu;   // exclude self
    }
    // round-1 histogram on prefix bits [15:8], warp-aggregated
#pragma unroll
    for (int i = 0; i < 8; i++) {
        unsigned bin = p[i] >> 8;
        unsigned peers = __match_any_sync(0xFFFFFFFFu, bin);
        if ((peers & ((1u << lane) - 1u)) == 0u)
            atomicAdd(&hist[bin], (unsigned)__popc(peers));
    }
    __syncthreads();
    // scan 1
    {
        unsigned cnt = hist[t];
        unsigned v = cnt;
#pragma unroll
        for (int d = 1; d < 32; d <<= 1) {
            unsigned o = __shfl_up_sync(0xFFFFFFFFu, v, d);
            if (lane >= d) v += o;
        }
        if (lane == 31) wsum[t >> 5] = v;
        __syncthreads();
        unsigned woff = 0;
        for (int w = 0; w < (t >> 5); w++) woff += wsum[w];
        unsigned incl = v + woff;
        unsigned excl = incl - cnt;
        if (excl < KNN && incl >= KNN) { s_b1 = t; s_c1 = (int)excl; }
    }
    __syncthreads();
    unsigned b1 = (unsigned)s_b1;
    int c1 = s_c1;
    hist[t] = 0u;
    __syncthreads();
    // round-2 histogram on prefix bits [7:0] within bin b1
#pragma unroll
    for (int i = 0; i < 8; i++) {
        bool pred = (p[i] >> 8) == b1;
        unsigned act = __ballot_sync(0xFFFFFFFFu, pred);
        if (pred) {
            unsigned bin = p[i] & 255u;
            unsigned peers = __match_any_sync(act, bin);
            if ((peers & ((1u << lane) - 1u)) == 0u)
                atomicAdd(&hist[bin], (unsigned)__popc(peers));
        }
    }
    __syncthreads();
    int need2 = KNN - c1;
    // scan 2
    {
        unsigned cnt = hist[t];
        unsigned v = cnt;
#pragma unroll
        for (int d = 1; d < 32; d <<= 1) {
            unsigned o = __shfl_up_sync(0xFFFFFFFFu, v, d);
            if (lane >= d) v += o;
        }
        if (lane == 31) wsum[t >> 5] = v;
        __syncthreads();
        unsigned woff = 0;
        for (int w = 0; w < (t >> 5); w++) woff += wsum[w];
        unsigned incl = v + woff;
        unsigned excl = incl - cnt;
        if ((int)excl < need2 && (int)incl >= need2) { s_b2 = t; s_c2 = (int)excl; }
    }
    __syncthreads();
    unsigned B = (b1 << 8) | (unsigned)s_b2;   // exact boundary prefix
    int c2 = s_c2;
    int need3 = need2 - c2;                    // take need3 from prefix == B
    int* out = g_idx + gp * KNN;
#pragma unroll
    for (int i = 0; i < 8; i++) {
        if (p[i] < B) {
            out[atomicAdd(&s_sel, 1)] = t * 8 + i;
        } else if (p[i] == B) {
            int c = atomicAdd(&s_cand, 1);
            if (c < CAND_MAX) cand_m[c] = t * 8 + i;
        }
    }
    __syncthreads();
    if (need3 <= 0) return;
    int cb = min(s_cand, CAND_MAX);
    // recompute exact keys for boundary candidates from point-major g_xt
    u64 myk = 0;
    if (t < cb) {
        int m = cand_m[t];
        const float4* xn = (const float4*)(g_xt + (size_t)gp * FIN);
        const float4* xm = (const float4*)(g_xt + (size_t)(b * NP + m) * FIN);
        float dot = 0.f;
#pragma unroll
        for (int f = 0; f < FIN / 4; f++) {
            float4 a = xn[f], c = xm[f];
            dot = fmaf(a.x, c.x, dot);
            dot = fmaf(a.y, c.y, dot);
            dot = fmaf(a.z, c.z, dot);
            dot = fmaf(a.w, c.w, dot);
        }
        float v = fmaf(dot, -2.f, g_sq[b * NP + m]);
        myk = (((u64)tkey(v)) << 32) | (unsigned)m;
        cand_k[t] = myk;
    }
    __syncthreads();
    if (t < cb) {
        int rank = 0;
        for (int j = 0; j < cb; j++)
            rank += (cand_k[j] < myk) ? 1 : 0;
        if (rank < need3) out[atomicAdd(&s_sel, 1)] = cand_m[t];
    }
}

// P[b,n,:] = A^T x + bias ; Q[b,n,:] = C^T x  (pre-transposed weights, f32x2)
__global__ __launch_bounds__(256, 2) void k_pq(const float* __restrict__ x,
                                               const float* __restrict__ bias) {
    extern __shared__ float sm[];
    float* Ash = sm;                 // [64][128]
    float* Csh = sm + 8192;          // [64][128]
    float* xs  = sm + 16384;         // [64][64]
    int b  = blockIdx.y;
    int n0 = blockIdx.x * 64;
    int tid = threadIdx.x;
#pragma unroll
    for (int i = 0; i < 8; i++) {
        int id = (tid + 256 * i) * 4;
        *(float4*)(Ash + id) = *(const float4*)(g_A + id);
        *(float4*)(Csh + id) = *(const float4*)(g_C + id);
    }
#pragma unroll
    for (int i = 0; i < 4; i++) {
        int id = tid + 256 * i;
        int f = id >> 4, c = (id & 15) * 4;
        *(float4*)(xs + f * 64 + c) = *(const float4*)(x + ((size_t)b * FIN + f) * NP + n0 + c);
    }
    __syncthreads();
    int tn = tid & 7, to = tid >> 3;
    int o0 = to * 4, nl0 = tn * 8;
    u64 accP[4][4], accQ[4][4];
    float4 bi = *(const float4*)(bias + o0);
    float bia[4] = {bi.x, bi.y, bi.z, bi.w};
#pragma unroll
    for (int i = 0; i < 4; i++) {
        u64 bd = dupf(bia[i]);
#pragma unroll
        for (int j = 0; j < 4; j++) { accP[i][j] = bd; accQ[i][j] = 0ull; }
    }
#pragma unroll 4
    for (int f = 0; f < 64; f++) {
        float4 a4 = *(float4*)(Ash + f * 128 + o0);
        float4 c4 = *(float4*)(Csh + f * 128 + o0);
        ulonglong2 x0 = *(ulonglong2*)(xs + f * 64 + nl0);
        ulonglong2 x1 = *(ulonglong2*)(xs + f * 64 + nl0 + 4);
        u64 xp[4] = {x0.x, x0.y, x1.x, x1.y};
        float aa[4] = {a4.x, a4.y, a4.z, a4.w};
        float cc[4] = {c4.x, c4.y, c4.z, c4.w};
#pragma unroll
        for (int i = 0; i < 4; i++) {
            u64 ad = dupf(aa[i]), cd = dupf(cc[i]);
#pragma unroll
            for (int j = 0; j < 4; j++) {
                accP[i][j] = fma2(ad, xp[j], accP[i][j]);
                accQ[i][j] = fma2(cd, xp[j], accQ[i][j]);
            }
        }
    }
#pragma unroll
    for (int jj = 0; jj < 8; jj++) {
        int j = jj >> 1, h = jj & 1;
        float pv[4], qv[4];
#pragma unroll
        for (int i = 0; i < 4; i++) {
            float2 p2 = unpack2(accP[i][j]); pv[i] = h ? p2.y : p2.x;
            float2 q2 = unpack2(accQ[i][j]); qv[i] = h ? q2.y : q2.x;
        }
        size_t base = (size_t)(b * NP + n0 + nl0 + jj) * FOUT + o0;
        *(float4*)(g_P + base) = make_float4(pv[0], pv[1], pv[2], pv[3]);
        *(float4*)(g_Q + base) = make_float4(qv[0], qv[1], qv[2], qv[3]);
    }
}

// Per (b,n): gather K neighbor Q columns; ymax/ymin = P + max/min_k Q;
// accumulate per-channel sum(y), sum(y^2) over edges.
__global__ __launch_bounds__(256) void k_edge() {
    __shared__ float bs1[FOUT], bs2[FOUT];
    int tid = threadIdx.x;
    int w = tid >> 5, lane = tid & 31;
    if (tid < FOUT) { bs1[tid] = 0.f; bs2[tid] = 0.f; }
    __syncthreads();
    int gp = blockIdx.x * 8 + w;
    int b  = gp >> 11;
    size_t pbase = (size_t)gp * FOUT + lane * 4;
    float4 p = *(const float4*)(g_P + pbase);
    const int* idx = g_idx + gp * KNN;
    const float INF = __int_as_float(0x7f800000);
    float4 qmax = make_float4(-INF, -INF, -INF, -INF);
    float4 qmin = make_float4(INF, INF, INF, INF);
    float4 s  = make_float4(0.f, 0.f, 0.f, 0.f);
    float4 s2 = make_float4(0.f, 0.f, 0.f, 0.f);
#pragma unroll 4
    for (int k = 0; k < KNN; k++) {
        int m = __ldg(idx + k);
        float4 q = *(const float4*)(g_Q + ((size_t)(b * NP + m)) * FOUT + lane * 4);
        qmax.x = fmaxf(qmax.x, q.x); qmax.y = fmaxf(qmax.y, q.y);
        qmax.z = fmaxf(qmax.z, q.z); qmax.w = fmaxf(qmax.w, q.w);
        qmin.x = fminf(qmin.x, q.x); qmin.y = fminf(qmin.y, q.y);
        qmin.z = fminf(qmin.z, q.z); qmin.w = fminf(qmin.w, q.w);
        s.x += q.x; s.y += q.y; s.z += q.z; s.w += q.w;
        s2.x = fmaf(q.x, q.x, s2.x); s2.y = fmaf(q.y, q.y, s2.y);
        s2.z = fmaf(q.z, q.z, s2.z); s2.w = fmaf(q.w, q.w, s2.w);
    }
    float4 ymax = make_float4(p.x + qmax.x, p.y + qmax.y, p.z + qmax.z, p.w + qmax.w);
    float4 ymin = make_float4(p.x + qmin.x, p.y + qmin.y, p.z + qmin.z, p.w + qmin.w);
    *(float4*)(g_ymax + pbase) = ymax;
    *(float4*)(g_ymin + pbase) = ymin;
    float s1a[4], ssa[4];
    float pp[4] = {p.x, p.y, p.z, p.w};
    float sa[4] = {s.x, s.y, s.z, s.w};
    float s2a[4] = {s2.x, s2.y, s2.z, s2.w};
#pragma unroll
    for (int i = 0; i < 4; i++) {
        s1a[i] = fmaf((float)KNN, pp[i], sa[i]);
        ssa[i] = fmaf(pp[i], fmaf((float)KNN, pp[i], 2.f * sa[i]), s2a[i]);
    }
#pragma unroll
    for (int i = 0; i < 4; i++) {
        atomicAdd(&bs1[lane * 4 + i], s1a[i]);
        atomicAdd(&bs2[lane * 4 + i], ssa[i]);
    }
    __syncthreads();
    if (tid < FOUT) {
        atomicAdd(&g_S1[tid], bs1[tid]);
        atomicAdd(&g_S2[tid], bs2[tid]);
    }
}

__global__ void k_stats(const float* __restrict__ gamma, const float* __restrict__ beta) {
    int o = threadIdx.x;
    const float inv = 1.f / (float)EDGES;
    float m   = g_S1[o] * inv;
    float var = fmaf(-m, m, g_S2[o] * inv);
    float sc  = gamma[o] * rsqrtf(var + 1e-5f);
    g_scale[o] = sc;
    g_shift[o] = fmaf(-m, sc, beta[o]);
}

// out[b,o,n] = relu(scale*(scale>=0 ? ymax : ymin) + shift), transposed write.
__global__ __launch_bounds__(256) void k_out(float* __restrict__ out) {
    __shared__ float sh[FOUT * 36];
    __shared__ float ssc[FOUT], ssf[FOUT];
    int b  = blockIdx.y;
    int n0 = blockIdx.x * 32;
    int tid = threadIdx.x;
    if (tid < FOUT) { ssc[tid] = g_scale[tid]; ssf[tid] = g_shift[tid]; }
    __syncthreads();
    int o  = tid & 127;
    int nh = tid >> 7;
    float sc = ssc[o], sf = ssf[o];
#pragma unroll
    for (int it = 0; it < 16; it++) {
        int nl = it * 2 + nh;
        size_t base = ((size_t)(b * NP + n0 + nl)) * FOUT + o;
        float vmax = g_ymax[base], vmin = g_ymin[base];
        float v = (sc >= 0.f) ? vmax : vmin;
        sh[o * 36 + nl] = fmaxf(fmaf(sc, v, sf), 0.f);
    }
    __syncthreads();
    int ow = tid >> 1;
    int h  = tid & 1;
    float* dst = out + ((size_t)(b * FOUT + ow)) * NP + n0 + h * 16;
    const float* src = sh + ow * 36 + h * 16;
#pragma unroll
    for (int j = 0; j < 4; j++)
        *(float4*)(dst + j * 4) = *(const float4*)(src + j * 4);
}

// ---------------- launch ----------------------------------------------------
extern "C" void kernel_launch(void* const* d_in, const int* in_sizes, int n_in,
                              void* d_out, int out_size) {
    const float* x     = (const float*)d_in[0];
    const float* W     = (const float*)d_in[1];
    const float* bias  = (const float*)d_in[2];
    const float* gamma = (const float*)d_in[3];
    const float* beta  = (const float*)d_in[4];
    float* out = (float*)d_out;

    const int GRAM_SMEM = 256 * 65 * 4;   // 66560 B
    const int PQ_SMEM   = (2 * 64 * 128 + 64 * 64) * 4;  // 81920 B
    cudaFuncSetAttribute(k_gram, cudaFuncAttributeMaxDynamicSharedMemorySize, GRAM_SMEM);
    cudaFuncSetAttribute(k_pq,   cudaFuncAttributeMaxDynamicSharedMemorySize, PQ_SMEM);

    k_zero<<<1, 128>>>();
    k_prep<<<32, 256>>>(W);
    k_sq<<<NPTS / 256, 256>>>(x);
    k_gram<<<dim3(136, 1, NB), 256, GRAM_SMEM>>>(x);
    k_select<<<NPTS, 256>>>();
    k_pq<<<dim3(NP / 64, NB), 256, PQ_SMEM>>>(x, bias);
    k_edge<<<NPTS / 8, 256>>>();
    k_stats<<<1, 128>>>(gamma, beta);
    k_out<<<dim3(NP / 32, NB), 256>>>(out);
}

// round 15
// speedup vs baseline: 1.3974x; 1.0351x over previous
#include <cuda_runtime.h>
#include <cstdint>

#define NB   16
#define FIN  64
#define FOUT 128
#define NP   2048
#define KNN  20
#define NPTS (NB * NP)            /* 32768 */
#define EDGES (NPTS * KNN)        /* 655360 */

typedef unsigned long long u64;

// ---------------- scratch (device globals: no allocations allowed) ----------
__device__ float          g_sq[NPTS];
__device__ float          g_xt[(size_t)NPTS * FIN];  // 8 MB point-major copy of x
__device__ unsigned short g_pre[(size_t)NPTS * NP];  // 128 MB: 16-bit sortable key prefixes
__device__ int            g_idx[NPTS * KNN];
__device__ float          g_A[FIN * FOUT];           // (W1-W2)^T  [f][o]
__device__ float          g_C[FIN * FOUT];           // W2^T       [f][o]
__device__ float          g_P[NPTS * FOUT];
__device__ float          g_Q[NPTS * FOUT];
__device__ float          g_ymax[NPTS * FOUT];
__device__ float          g_ymin[NPTS * FOUT];
__device__ float          g_S1[FOUT];
__device__ float          g_S2[FOUT];
__device__ float          g_scale[FOUT];
__device__ float          g_shift[FOUT];

// ---------------- f32x2 helpers (Blackwell packed fp32 FMA) -----------------
__device__ __forceinline__ u64 fma2(u64 a, u64 b, u64 c) {
    u64 d;
    asm("fma.rn.f32x2 %0, %1, %2, %3;" : "=l"(d) : "l"(a), "l"(b), "l"(c));
    return d;
}
__device__ __forceinline__ u64 dupf(float a) {
    u64 d;
    unsigned u = __float_as_uint(a);
    asm("mov.b64 %0, {%1, %1};" : "=l"(d) : "r"(u));
    return d;
}
__device__ __forceinline__ float2 unpack2(u64 d) {
    unsigned lo, hi;
    asm("mov.b64 {%0, %1}, %2;" : "=r"(lo), "=r"(hi) : "l"(d));
    return make_float2(__uint_as_float(lo), __uint_as_float(hi));
}
// monotone float -> unsigned-sortable transform
__device__ __forceinline__ unsigned tkey(float f) {
    unsigned b = __float_as_uint(f);
    return ((int)b < 0) ? ~b : (b | 0x80000000u);
}

// ---------------- kernels ---------------------------------------------------

__global__ void k_zero() {
    int t = threadIdx.x;
    if (t < FOUT) { g_S1[t] = 0.f; g_S2[t] = 0.f; }
}

// sq[b,n] = sum_f x^2 ; also emit point-major transposed copy g_xt[n][f]
__global__ void k_sq(const float* __restrict__ x) {
    int gp = blockIdx.x * blockDim.x + threadIdx.x;
    if (gp >= NPTS) return;
    int b = gp >> 11, n = gp & (NP - 1);
    const float* p = x + (size_t)b * FIN * NP + n;
    float* xt = g_xt + (size_t)gp * FIN;
    float s = 0.f;
#pragma unroll
    for (int f = 0; f < FIN; f++) {
        float v = p[(size_t)f * NP];
        xt[f] = v;
        s = fmaf(v, v, s);
    }
    g_sq[gp] = s;
}

// Transpose weights: g_A[f][o] = W[o][f]-W[o][64+f], g_C[f][o] = W[o][64+f]
__global__ void k_prep(const float* __restrict__ W) {
    int id = blockIdx.x * 256 + threadIdx.x;   // 0..8191
    if (id >= FIN * FOUT) return;
    int f = id >> 7, o = id & 127;
    float w1 = W[o * 128 + f], w2 = W[o * 128 + 64 + f];
    g_A[f * 128 + o] = w1 - w2;
    g_C[f * 128 + o] = w2;
}

// Symmetric Gram, lower-triangle 128x128 tiles. Stores ONLY the 16-bit
// sortable prefix of key = sq[m]-2G (half the DRAM bytes of full keys).
__global__ __launch_bounds__(256, 2) void k_gram(const float* __restrict__ x) {
    extern __shared__ float sm[];
    float* As = sm;               // [64][128]
    float* Bs = sm + 64 * 128;    // [64][128]
    int b = blockIdx.z;
    int kk = blockIdx.x;
    int ti = (int)((sqrtf(8.f * kk + 1.f) - 1.f) * 0.5f);
    while ((ti + 1) * (ti + 2) / 2 <= kk) ti++;
    while (ti * (ti + 1) / 2 > kk) ti--;
    int tj = kk - ti * (ti + 1) / 2;
    int n0 = ti * 128;            // rows
    int m0 = tj * 128;            // cols
    int tid = threadIdx.x;
    const float* xb = x + (size_t)b * FIN * NP;
#pragma unroll
    for (int i = 0; i < 8; i++) {
        int flat = (tid + 256 * i) * 4;
        int k = flat >> 7;
        int c = flat & 127;
        *(float4*)(As + k * 128 + c) = *(const float4*)(xb + (size_t)k * NP + n0 + c);
        *(float4*)(Bs + k * 128 + c) = *(const float4*)(xb + (size_t)k * NP + m0 + c);
    }
    __syncthreads();
    int tx = tid & 15, ty = tid >> 4;
    u64 acc[8][4];
#pragma unroll
    for (int i = 0; i < 8; i++)
#pragma unroll
        for (int j = 0; j < 4; j++) acc[i][j] = 0ull;

#pragma unroll 4
    for (int k = 0; k < 64; k++) {
        float4 a0 = *(float4*)(As + k * 128 + ty * 8);
        float4 a1 = *(float4*)(As + k * 128 + ty * 8 + 4);
        ulonglong2 bv0 = *(ulonglong2*)(Bs + k * 128 + tx * 8);
        ulonglong2 bv1 = *(ulonglong2*)(Bs + k * 128 + tx * 8 + 4);
        float av[8] = {a0.x, a0.y, a0.z, a0.w, a1.x, a1.y, a1.z, a1.w};
        u64 bv[4] = {bv0.x, bv0.y, bv1.x, bv1.y};
#pragma unroll
        for (int i = 0; i < 8; i++) {
            u64 ad = dupf(av[i]);
#pragma unroll
            for (int j = 0; j < 4; j++) acc[i][j] = fma2(ad, bv[j], acc[i][j]);
        }
    }
    float gf[8][8];
#pragma unroll
    for (int i = 0; i < 8; i++)
#pragma unroll
        for (int j = 0; j < 4; j++) {
            float2 p = unpack2(acc[i][j]);
            gf[i][2 * j] = p.x; gf[i][2 * j + 1] = p.y;
        }
    // direct tile: rows n0+ty*8+i, cols m0+tx*8+k
    {
        float sqm[8];
        *(float4*)sqm       = *(const float4*)(g_sq + b * NP + m0 + tx * 8);
        *(float4*)(sqm + 4) = *(const float4*)(g_sq + b * NP + m0 + tx * 8 + 4);
#pragma unroll
        for (int i = 0; i < 8; i++) {
            unsigned q[4];
#pragma unroll
            for (int j = 0; j < 4; j++) {
                unsigned lo = tkey(fmaf(gf[i][2 * j],     -2.f, sqm[2 * j]))     >> 16;
                unsigned hi = tkey(fmaf(gf[i][2 * j + 1], -2.f, sqm[2 * j + 1])) >> 16;
                q[j] = lo | (hi << 16);
            }
            unsigned short* op = g_pre + ((size_t)(b * NP + n0 + ty * 8 + i)) * NP + m0 + tx * 8;
            *(uint4*)op = make_uint4(q[0], q[1], q[2], q[3]);
        }
    }
    // transposed tile (off-diagonal only): rows m0+ty*8+r, cols n0+tx*8+c
    if (ti != tj) {
        __syncthreads();
        int s = tid;
        float* slots = sm;
#pragma unroll
        for (int k = 0; k < 8; k++)
#pragma unroll
            for (int i = 0; i < 8; i++)
                slots[s * 65 + k * 8 + ((i + s) & 7)] = gf[i][k];
        __syncthreads();
        int s2 = ((tid & 15) << 4) | (tid >> 4);
        float sqn[8];
        *(float4*)sqn       = *(const float4*)(g_sq + b * NP + n0 + tx * 8);
        *(float4*)(sqn + 4) = *(const float4*)(g_sq + b * NP + n0 + tx * 8 + 4);
#pragma unroll
        for (int r = 0; r < 8; r++) {
            unsigned q[4];
#pragma unroll
            for (int j = 0; j < 4; j++) {
                float w0 = slots[s2 * 65 + r * 8 + ((2 * j + s2) & 7)];
                float w1 = slots[s2 * 65 + r * 8 + ((2 * j + 1 + s2) & 7)];
                unsigned lo = tkey(fmaf(w0, -2.f, sqn[2 * j]))     >> 16;
                unsigned hi = tkey(fmaf(w1, -2.f, sqn[2 * j + 1])) >> 16;
                q[j] = lo | (hi << 16);
            }
            unsigned short* op = g_pre + ((size_t)(b * NP + m0 + ty * 8 + r)) * NP + n0 + tx * 8;
            *(uint4*)op = make_uint4(q[0], q[1], q[2], q[3]);
        }
    }
}

// Two-round 8-bit radix on 16-bit prefixes with PER-WARP histogram copies
// (plain shared atomicAdd, no match_any: 1 shift + 1 ATOMS per key; ATOMS is
// LSU-pipe, unloading the ALU bottleneck). Scan phase sums the 8 copies.
// Boundary candidates re-ranked by exact distance from point-major g_xt.
#define CAND_MAX 128
__global__ __launch_bounds__(256) void k_select() {
    int gp = blockIdx.x;                       // b*NP + n
    int n  = gp & (NP - 1);
    int b  = gp >> 11;
    const uint4* row4 = (const uint4*)(g_pre + (size_t)gp * NP);
    __shared__ unsigned hist[8 * 256];         // [warp][bin]
    __shared__ int  cand_m[CAND_MAX];
    __shared__ u64  cand_k[CAND_MAX];
    __shared__ unsigned wsum[8];
    __shared__ int s_sel, s_cand, s_b1, s_c1, s_b2, s_c2;
    int t = threadIdx.x;
    int lane = t & 31, w = t >> 5;
    unsigned* myh = hist + w * 256;
#pragma unroll
    for (int i = 0; i < 8; i++) hist[t + 256 * i] = 0u;
    if (t == 0) { s_sel = 0; s_cand = 0; }
    __syncthreads();

    unsigned p[8];
    {
        uint4 a = __ldcs(row4 + t);
        p[0] = a.x & 0xFFFFu; p[1] = a.x >> 16;
        p[2] = a.y & 0xFFFFu; p[3] = a.y >> 16;
        p[4] = a.z & 0xFFFFu; p[5] = a.z >> 16;
        p[6] = a.w & 0xFFFFu; p[7] = a.w >> 16;
        int d = n - t * 8;
        if (d >= 0 && d < 8) p[d] = 0xFFFFu;   // exclude self
    }
    // round-1: per-warp histogram on prefix bits [15:8]
#pragma unroll
    for (int i = 0; i < 8; i++)
        atomicAdd(&myh[p[i] >> 8], 1u);
    __syncthreads();
    // reduce 8 copies + scan 1
    {
        unsigned cnt = 0;
#pragma unroll
        for (int wi = 0; wi < 8; wi++) cnt += hist[wi * 256 + t];
        unsigned v = cnt;
#pragma unroll
        for (int d = 1; d < 32; d <<= 1) {
            unsigned o = __shfl_up_sync(0xFFFFFFFFu, v, d);
            if (lane >= d) v += o;
        }
        if (lane == 31) wsum[w] = v;
        __syncthreads();
        unsigned woff = 0;
        for (int wi = 0; wi < w; wi++) woff += wsum[wi];
        unsigned incl = v + woff;
        unsigned excl = incl - cnt;
        if (excl < KNN && incl >= KNN) { s_b1 = t; s_c1 = (int)excl; }
    }
    __syncthreads();
    unsigned b1 = (unsigned)s_b1;
    int c1 = s_c1;
#pragma unroll
    for (int i = 0; i < 8; i++) hist[t + 256 * i] = 0u;
    __syncthreads();
    // round-2: per-warp histogram on prefix bits [7:0] within bin b1
#pragma unroll
    for (int i = 0; i < 8; i++)
        if ((p[i] >> 8) == b1) atomicAdd(&myh[p[i] & 255u], 1u);
    __syncthreads();
    int need2 = KNN - c1;
    // reduce + scan 2
    {
        unsigned cnt = 0;
#pragma unroll
        for (int wi = 0; wi < 8; wi++) cnt += hist[wi * 256 + t];
        unsigned v = cnt;
#pragma unroll
        for (int d = 1; d < 32; d <<= 1) {
            unsigned o = __shfl_up_sync(0xFFFFFFFFu, v, d);
            if (lane >= d) v += o;
        }
        if (lane == 31) wsum[w] = v;
        __syncthreads();
        unsigned woff = 0;
        for (int wi = 0; wi < w; wi++) woff += wsum[wi];
        unsigned incl = v + woff;
        unsigned excl = incl - cnt;
        if ((int)excl < need2 && (int)incl >= need2) { s_b2 = t; s_c2 = (int)excl; }
    }
    __syncthreads();
    unsigned B = (b1 << 8) | (unsigned)s_b2;   // exact boundary prefix
    int c2 = s_c2;
    int need3 = need2 - c2;                    // take need3 from prefix == B
    int* out = g_idx + gp * KNN;
#pragma unroll
    for (int i = 0; i < 8; i++) {
        if (p[i] < B) {
            out[atomicAdd(&s_sel, 1)] = t * 8 + i;
        } else if (p[i] == B) {
            int c = atomicAdd(&s_cand, 1);
            if (c < CAND_MAX) cand_m[c] = t * 8 + i;
        }
    }
    __syncthreads();
    if (need3 <= 0) return;
    int cb = min(s_cand, CAND_MAX);
    // recompute exact keys for boundary candidates from point-major g_xt
    u64 myk = 0;
    if (t < cb) {
        int m = cand_m[t];
        const float4* xn = (const float4*)(g_xt + (size_t)gp * FIN);
        const float4* xm = (const float4*)(g_xt + (size_t)(b * NP + m) * FIN);
        float dot = 0.f;
#pragma unroll
        for (int f = 0; f < FIN / 4; f++) {
            float4 a = xn[f], c = xm[f];
            dot = fmaf(a.x, c.x, dot);
            dot = fmaf(a.y, c.y, dot);
            dot = fmaf(a.z, c.z, dot);
            dot = fmaf(a.w, c.w, dot);
        }
        float v = fmaf(dot, -2.f, g_sq[b * NP + m]);
        myk = (((u64)tkey(v)) << 32) | (unsigned)m;
        cand_k[t] = myk;
    }
    __syncthreads();
    if (t < cb) {
        int rank = 0;
        for (int j = 0; j < cb; j++)
            rank += (cand_k[j] < myk) ? 1 : 0;
        if (rank < need3) out[atomicAdd(&s_sel, 1)] = cand_m[t];
    }
}

// P[b,n,:] = A^T x + bias ; Q[b,n,:] = C^T x  (pre-transposed weights, f32x2)
__global__ __launch_bounds__(256, 2) void k_pq(const float* __restrict__ x,
                                               const float* __restrict__ bias) {
    extern __shared__ float sm[];
    float* Ash = sm;                 // [64][128]
    float* Csh = sm + 8192;          // [64][128]
    float* xs  = sm + 16384;         // [64][64]
    int b  = blockIdx.y;
    int n0 = blockIdx.x * 64;
    int tid = threadIdx.x;
#pragma unroll
    for (int i = 0; i < 8; i++) {
        int id = (tid + 256 * i) * 4;
        *(float4*)(Ash + id) = *(const float4*)(g_A + id);
        *(float4*)(Csh + id) = *(const float4*)(g_C + id);
    }
#pragma unroll
    for (int i = 0; i < 4; i++) {
        int id = tid + 256 * i;
        int f = id >> 4, c = (id & 15) * 4;
        *(float4*)(xs + f * 64 + c) = *(const float4*)(x + ((size_t)b * FIN + f) * NP + n0 + c);
    }
    __syncthreads();
    int tn = tid & 7, to = tid >> 3;
    int o0 = to * 4, nl0 = tn * 8;
    u64 accP[4][4], accQ[4][4];
    float4 bi = *(const float4*)(bias + o0);
    float bia[4] = {bi.x, bi.y, bi.z, bi.w};
#pragma unroll
    for (int i = 0; i < 4; i++) {
        u64 bd = dupf(bia[i]);
#pragma unroll
        for (int j = 0; j < 4; j++) { accP[i][j] = bd; accQ[i][j] = 0ull; }
    }
#pragma unroll 4
    for (int f = 0; f < 64; f++) {
        float4 a4 = *(float4*)(Ash + f * 128 + o0);
        float4 c4 = *(float4*)(Csh + f * 128 + o0);
        ulonglong2 x0 = *(ulonglong2*)(xs + f * 64 + nl0);
        ulonglong2 x1 = *(ulonglong2*)(xs + f * 64 + nl0 + 4);
        u64 xp[4] = {x0.x, x0.y, x1.x, x1.y};
        float aa[4] = {a4.x, a4.y, a4.z, a4.w};
        float cc[4] = {c4.x, c4.y, c4.z, c4.w};
#pragma unroll
        for (int i = 0; i < 4; i++) {
            u64 ad = dupf(aa[i]), cd = dupf(cc[i]);
#pragma unroll
            for (int j = 0; j < 4; j++) {
                accP[i][j] = fma2(ad, xp[j], accP[i][j]);
                accQ[i][j] = fma2(cd, xp[j], accQ[i][j]);
            }
        }
    }
#pragma unroll
    for (int jj = 0; jj < 8; jj++) {
        int j = jj >> 1, h = jj & 1;
        float pv[4], qv[4];
#pragma unroll
        for (int i = 0; i < 4; i++) {
            float2 p2 = unpack2(accP[i][j]); pv[i] = h ? p2.y : p2.x;
            float2 q2 = unpack2(accQ[i][j]); qv[i] = h ? q2.y : q2.x;
        }
        size_t base = (size_t)(b * NP + n0 + nl0 + jj) * FOUT + o0;
        *(float4*)(g_P + base) = make_float4(pv[0], pv[1], pv[2], pv[3]);
        *(float4*)(g_Q + base) = make_float4(qv[0], qv[1], qv[2], qv[3]);
    }
}

// Per (b,n): gather K neighbor Q columns; ymax/ymin = P + max/min_k Q;
// accumulate per-channel sum(y), sum(y^2) over edges.
__global__ __launch_bounds__(256) void k_edge() {
    __shared__ float bs1[FOUT], bs2[FOUT];
    int tid = threadIdx.x;
    int w = tid >> 5, lane = tid & 31;
    if (tid < FOUT) { bs1[tid] = 0.f; bs2[tid] = 0.f; }
    __syncthreads();
    int gp = blockIdx.x * 8 + w;
    int b  = gp >> 11;
    size_t pbase = (size_t)gp * FOUT + lane * 4;
    float4 p = *(const float4*)(g_P + pbase);
    const int* idx = g_idx + gp * KNN;
    const float INF = __int_as_float(0x7f800000);
    float4 qmax = make_float4(-INF, -INF, -INF, -INF);
    float4 qmin = make_float4(INF, INF, INF, INF);
    float4 s  = make_float4(0.f, 0.f, 0.f, 0.f);
    float4 s2 = make_float4(0.f, 0.f, 0.f, 0.f);
#pragma unroll 4
    for (int k = 0; k < KNN; k++) {
        int m = __ldg(idx + k);
        float4 q = *(const float4*)(g_Q + ((size_t)(b * NP + m)) * FOUT + lane * 4);
        qmax.x = fmaxf(qmax.x, q.x); qmax.y = fmaxf(qmax.y, q.y);
        qmax.z = fmaxf(qmax.z, q.z); qmax.w = fmaxf(qmax.w, q.w);
        qmin.x = fminf(qmin.x, q.x); qmin.y = fminf(qmin.y, q.y);
        qmin.z = fminf(qmin.z, q.z); qmin.w = fminf(qmin.w, q.w);
        s.x += q.x; s.y += q.y; s.z += q.z; s.w += q.w;
        s2.x = fmaf(q.x, q.x, s2.x); s2.y = fmaf(q.y, q.y, s2.y);
        s2.z = fmaf(q.z, q.z, s2.z); s2.w = fmaf(q.w, q.w, s2.w);
    }
    float4 ymax = make_float4(p.x + qmax.x, p.y + qmax.y, p.z + qmax.z, p.w + qmax.w);
    float4 ymin = make_float4(p.x + qmin.x, p.y + qmin.y, p.z + qmin.z, p.w + qmin.w);
    *(float4*)(g_ymax + pbase) = ymax;
    *(float4*)(g_ymin + pbase) = ymin;
    float s1a[4], ssa[4];
    float pp[4] = {p.x, p.y, p.z, p.w};
    float sa[4] = {s.x, s.y, s.z, s.w};
    float s2a[4] = {s2.x, s2.y, s2.z, s2.w};
#pragma unroll
    for (int i = 0; i < 4; i++) {
        s1a[i] = fmaf((float)KNN, pp[i], sa[i]);
        ssa[i] = fmaf(pp[i], fmaf((float)KNN, pp[i], 2.f * sa[i]), s2a[i]);
    }
#pragma unroll
    for (int i = 0; i < 4; i++) {
        atomicAdd(&bs1[lane * 4 + i], s1a[i]);
        atomicAdd(&bs2[lane * 4 + i], ssa[i]);
    }
    __syncthreads();
    if (tid < FOUT) {
        atomicAdd(&g_S1[tid], bs1[tid]);
        atomicAdd(&g_S2[tid], bs2[tid]);
    }
}

__global__ void k_stats(const float* __restrict__ gamma, const float* __restrict__ beta) {
    int o = threadIdx.x;
    const float inv = 1.f / (float)EDGES;
    float m   = g_S1[o] * inv;
    float var = fmaf(-m, m, g_S2[o] * inv);
    float sc  = gamma[o] * rsqrtf(var + 1e-5f);
    g_scale[o] = sc;
    g_shift[o] = fmaf(-m, sc, beta[o]);
}

// out[b,o,n] = relu(scale*(scale>=0 ? ymax : ymin) + shift), transposed write.
__global__ __launch_bounds__(256) void k_out(float* __restrict__ out) {
    __shared__ float sh[FOUT * 36];
    __shared__ float ssc[FOUT], ssf[FOUT];
    int b  = blockIdx.y;
    int n0 = blockIdx.x * 32;
    int tid = threadIdx.x;
    if (tid < FOUT) { ssc[tid] = g_scale[tid]; ssf[tid] = g_shift[tid]; }
    __syncthreads();
    int o  = tid & 127;
    int nh = tid >> 7;
    float sc = ssc[o], sf = ssf[o];
#pragma unroll
    for (int it = 0; it < 16; it++) {
        int nl = it * 2 + nh;
        size_t base = ((size_t)(b * NP + n0 + nl)) * FOUT + o;
        float vmax = g_ymax[base], vmin = g_ymin[base];
        float v = (sc >= 0.f) ? vmax : vmin;
        sh[o * 36 + nl] = fmaxf(fmaf(sc, v, sf), 0.f);
    }
    __syncthreads();
    int ow = tid >> 1;
    int h  = tid & 1;
    float* dst = out + ((size_t)(b * FOUT + ow)) * NP + n0 + h * 16;
    const float* src = sh + ow * 36 + h * 16;
#pragma unroll
    for (int j = 0; j < 4; j++)
        *(float4*)(dst + j * 4) = *(const float4*)(src + j * 4);
}

// ---------------- launch ----------------------------------------------------
extern "C" void kernel_launch(void* const* d_in, const int* in_sizes, int n_in,
                              void* d_out, int out_size) {
    const float* x     = (const float*)d_in[0];
    const float* W     = (const float*)d_in[1];
    const float* bias  = (const float*)d_in[2];
    const float* gamma = (const float*)d_in[3];
    const float* beta  = (const float*)d_in[4];
    float* out = (float*)d_out;

    const int GRAM_SMEM = 256 * 65 * 4;   // 66560 B
    const int PQ_SMEM   = (2 * 64 * 128 + 64 * 64) * 4;  // 81920 B
    cudaFuncSetAttribute(k_gram, cudaFuncAttributeMaxDynamicSharedMemorySize, GRAM_SMEM);
    cudaFuncSetAttribute(k_pq,   cudaFuncAttributeMaxDynamicSharedMemorySize, PQ_SMEM);

    k_zero<<<1, 128>>>();
    k_prep<<<32, 256>>>(W);
    k_sq<<<NPTS / 256, 256>>>(x);
    k_gram<<<dim3(136, 1, NB), 256, GRAM_SMEM>>>(x);
    k_select<<<NPTS, 256>>>();
    k_pq<<<dim3(NP / 64, NB), 256, PQ_SMEM>>>(x, bias);
    k_edge<<<NPTS / 8, 256>>>();
    k_stats<<<1, 128>>>(gamma, beta);
    k_out<<<dim3(NP / 32, NB), 256>>>(out);
}